// round 15
// baseline (speedup 1.0000x reference)
#include <cuda_runtime.h>
#include <math.h>

#define RES   14
#define NN    196          // RES*RES tokens
#define BATCH 128
#define DIMX  384
#define NH    12
#define KDIM  32
#define VDIM  128
#define HDIM  192          // per-head q+k+v = 32+32+128
#define QKVD  2304
#define VAD   1536
#define MTOT  (BATCH*NN)   // 25088

// Scratch (device globals — no allocation allowed in kernel_launch)
__device__ float g_qkv[(size_t)MTOT * QKVD];   // ~231 MB
__device__ float g_att[(size_t)MTOT * VAD];    // ~154 MB

// ---------------------------------------------------------------------------
// tf32 round-to-nearest conversion (unbiased; HW truncation would bias)
// ---------------------------------------------------------------------------
__device__ __forceinline__ unsigned f2tf32(float x) {
    unsigned r;
    asm("cvt.rna.tf32.f32 %0, %1;" : "=r"(r) : "f"(x));
    return r;
}

__device__ __forceinline__ void mma_tf32(float c[4], const unsigned a[4],
                                         const unsigned b[2]) {
    asm volatile(
        "mma.sync.aligned.m16n8k8.row.col.f32.tf32.tf32.f32 "
        "{%0,%1,%2,%3}, {%4,%5,%6,%7}, {%8,%9}, {%0,%1,%2,%3};"
        : "+f"(c[0]), "+f"(c[1]), "+f"(c[2]), "+f"(c[3])
        : "r"(a[0]), "r"(a[1]), "r"(a[2]), "r"(a[3]), "r"(b[0]), "r"(b[1]));
}

// ---------------------------------------------------------------------------
// tf32 tensor-core GEMM + fused BN:
//   C[m][n] = (sum_k A[m][k]*B[n][k]) * inv[n] + add[n]
// A: [M x K] row-major, B (weights): [N x K] row-major == col-major KxN,
// which is exactly mma.sync's .col B operand.
// CTA tile 128x128x32, 8 warps (4m x 2n), warp tile 32x64 (2x8 m16n8k8).
// SMEM staged in fragment order [tile][kstep][lane][reg] with a +2*ks lane
// rotation -> conflict-free scatter STS and conflict-free LDS.128/LDS.64.
// ---------------------------------------------------------------------------
template<int Kdim, int Ndim>
__global__ __launch_bounds__(256, 2)
void gemm_tf32_bn(const float* __restrict__ A,
                  const float* __restrict__ Bm,
                  const float* __restrict__ gamma,
                  const float* __restrict__ beta,
                  const float* __restrict__ mean,
                  const float* __restrict__ var,
                  float* __restrict__ C)
{
    __shared__ unsigned sA[8 * 4 * 32 * 4];   // 16 KB: [mt][ks][lane][reg4]
    __shared__ unsigned sB[16 * 4 * 32 * 2];  // 16 KB: [nt][ks][lane][reg2]
    __shared__ float sInv[128], sAdd[128];

    const int t  = threadIdx.x;
    const int l  = t & 31;
    const int w  = t >> 5;
    const int wm = w & 3;          // 0..3  (m)
    const int wn = w >> 2;         // 0..1  (n)
    const int m0 = blockIdx.y * 128;
    const int n0 = blockIdx.x * 128;

    if (t < 128) {
        float iv = gamma[n0 + t] * rsqrtf(var[n0 + t] + 1e-5f);
        sInv[t] = iv;
        sAdd[t] = beta[n0 + t] - mean[n0 + t] * iv;
    }

    float acc[2][8][4];
    #pragma unroll
    for (int i = 0; i < 2; i++)
        #pragma unroll
        for (int j = 0; j < 8; j++)
            #pragma unroll
            for (int r = 0; r < 4; r++) acc[i][j][r] = 0.f;

    #pragma unroll 1
    for (int k0 = 0; k0 < Kdim; k0 += 32) {
        __syncthreads();   // previous iter's fragment reads done

        // ---- stage A (128x32) into fragment-order smem ----
        #pragma unroll
        for (int p = 0; p < 4; p++) {
            int idx = p * 256 + t;            // 0..1023 float4s
            int row = idx >> 3, c4 = idx & 7;
            float4 v = *reinterpret_cast<const float4*>(
                &A[(size_t)(m0 + row) * Kdim + k0 + c4 * 4]);
            int mt = row >> 4, r = row & 15, ks = c4 >> 1;
            int reg = (r >> 3) + 2 * (c4 & 1);
            unsigned* dst = &sA[(mt * 4 + ks) * 128];
            int pb = (r & 7) * 4 + 2 * ks;    // rotated lane position
            dst[((pb + 0) & 31) * 4 + reg] = f2tf32(v.x);
            dst[((pb + 1) & 31) * 4 + reg] = f2tf32(v.y);
            dst[((pb + 2) & 31) * 4 + reg] = f2tf32(v.z);
            dst[((pb + 3) & 31) * 4 + reg] = f2tf32(v.w);
        }
        // ---- stage B (128x32) ----
        #pragma unroll
        for (int p = 0; p < 4; p++) {
            int idx = p * 256 + t;
            int row = idx >> 3, c4 = idx & 7;
            float4 v = *reinterpret_cast<const float4*>(
                &Bm[(size_t)(n0 + row) * Kdim + k0 + c4 * 4]);
            int nt = row >> 3, nl = row & 7, ks = c4 >> 1;
            int reg = c4 & 1;
            unsigned* dst = &sB[(nt * 4 + ks) * 64];
            int pb = nl * 4 + 2 * ks;
            dst[((pb + 0) & 31) * 2 + reg] = f2tf32(v.x);
            dst[((pb + 1) & 31) * 2 + reg] = f2tf32(v.y);
            dst[((pb + 2) & 31) * 2 + reg] = f2tf32(v.z);
            dst[((pb + 3) & 31) * 2 + reg] = f2tf32(v.w);
        }
        __syncthreads();

        // ---- 4 k-steps of m16n8k8 ----
        #pragma unroll
        for (int ks = 0; ks < 4; ks++) {
            const int rl = (l + 2 * ks) & 31;
            unsigned a[2][4], b[8][2];
            #pragma unroll
            for (int i = 0; i < 2; i++) {
                uint4 av = *reinterpret_cast<const uint4*>(
                    &sA[(((wm * 2 + i) * 4 + ks) * 32 + rl) * 4]);
                a[i][0] = av.x; a[i][1] = av.y; a[i][2] = av.z; a[i][3] = av.w;
            }
            #pragma unroll
            for (int j = 0; j < 8; j++) {
                uint2 bv = *reinterpret_cast<const uint2*>(
                    &sB[(((wn * 8 + j) * 4 + ks) * 32 + rl) * 2]);
                b[j][0] = bv.x; b[j][1] = bv.y;
            }
            #pragma unroll
            for (int i = 0; i < 2; i++)
                #pragma unroll
                for (int j = 0; j < 8; j++)
                    mma_tf32(acc[i][j], a[i], b[j]);
        }
    }

    // ---- BN epilogue ----
    const int gid = l >> 2, tid4 = l & 3;
    #pragma unroll
    for (int i = 0; i < 2; i++) {
        const int m = m0 + wm * 32 + i * 16 + gid;
        #pragma unroll
        for (int j = 0; j < 8; j++) {
            const int nb = wn * 64 + j * 8 + tid4 * 2;
            const float i0 = sInv[nb], a0 = sAdd[nb];
            const float i1 = sInv[nb + 1], a1 = sAdd[nb + 1];
            float2 o0, o1;
            o0.x = acc[i][j][0] * i0 + a0;
            o0.y = acc[i][j][1] * i1 + a1;
            o1.x = acc[i][j][2] * i0 + a0;
            o1.y = acc[i][j][3] * i1 + a1;
            *reinterpret_cast<float2*>(&C[(size_t)m * Ndim + n0 + nb]) = o0;
            *reinterpret_cast<float2*>(&C[(size_t)(m + 8) * Ndim + n0 + nb]) = o1;
        }
    }
}

// ---------------------------------------------------------------------------
// Attention: one CTA per (batch, head). 256 threads; thread i<196 owns query i.
// smem: scores[196][197] (stride-197 => bank-conflict-free), kv staging, bias.
// Softmax kept unnormalized (1/sum folded into PV). SiLU fused into store.
// ---------------------------------------------------------------------------
__global__ __launch_bounds__(256, 1)
void attn_kernel(const float* __restrict__ biases)
{
    extern __shared__ float sh[];
    float* s_sh    = sh;                      // 196*197 scores (also q staging)
    float* kv_sh   = sh + NN * 197;           // 196*32 (k, reused for v tiles)
    float* bias_sh = kv_sh + NN * KDIM;       // 196

    const int bh = blockIdx.x;
    const int b  = bh / NH;
    const int h  = bh % NH;
    const int t  = threadIdx.x;

    const float* base = g_qkv + (size_t)b * NN * QKVD + h * HDIM;

    for (int i = t; i < NN; i += 256) bias_sh[i] = biases[h * NN + i];
    for (int e = t; e < NN * KDIM; e += 256) {
        int n = e >> 5, d = e & 31;
        s_sh[e]  = base[(size_t)n * QKVD + d];          // q
        kv_sh[e] = base[(size_t)n * QKVD + KDIM + d];   // k
    }
    __syncthreads();

    float q[KDIM];
    if (t < NN) {
        #pragma unroll
        for (int d = 0; d < KDIM; d++) q[d] = s_sh[t * KDIM + d];
    }
    __syncthreads();   // s_sh free for scores now

    float* srow = s_sh + t * 197;
    float rmax = -1e30f;
    if (t < NN) {
        const int yi = t / RES, xi = t % RES;
        int j = 0;
        for (int yj = 0; yj < RES; yj++) {
            const int dy = abs(yi - yj) * RES;
            #pragma unroll
            for (int xj = 0; xj < RES; xj++, j++) {
                float acc = 0.f;
                const float* krow = kv_sh + j * KDIM;   // broadcast read
                #pragma unroll
                for (int d = 0; d < KDIM; d++)
                    acc = fmaf(q[d], krow[d], acc);
                float val = acc * 0.17677669529663687f + bias_sh[dy + abs(xi - xj)];
                srow[j] = val;
                rmax = fmaxf(rmax, val);
            }
        }
    }

    float rs = 0.f;
    if (t < NN) {
        for (int j = 0; j < NN; j++) {
            float e = __expf(srow[j] - rmax);
            srow[j] = e;
            rs += e;
        }
        rs = 1.0f / rs;
    }
    __syncthreads();   // everyone done with kv_sh(k) before v overwrites it

    float* out_base = g_att + (size_t)b * NN * VAD + h * VDIM;
    for (int dt = 0; dt < VDIM; dt += 16) {
        for (int e = t; e < NN * 16; e += 256) {
            int n = e >> 4, d = e & 15;
            kv_sh[e] = base[(size_t)n * QKVD + 2 * KDIM + dt + d];
        }
        __syncthreads();
        if (t < NN) {
            float acc[16];
            #pragma unroll
            for (int d = 0; d < 16; d++) acc[d] = 0.f;
            for (int j = 0; j < NN; j++) {
                float wgt = srow[j];                   // stride-197: conflict-free
                const float* vrow = kv_sh + j * 16;    // broadcast read
                #pragma unroll
                for (int d = 0; d < 16; d++)
                    acc[d] = fmaf(wgt, vrow[d], acc[d]);
            }
            #pragma unroll
            for (int d = 0; d < 16; d++) {
                float x = acc[d] * rs;
                float sig = 1.0f / (1.0f + __expf(-x));
                out_base[(size_t)t * VAD + dt + d] = x * sig;   // SiLU fused
            }
        }
        __syncthreads();
    }
}

// ---------------------------------------------------------------------------
extern "C" void kernel_launch(void* const* d_in, const int* in_sizes, int n_in,
                              void* d_out, int out_size)
{
    const float* x        = (const float*)d_in[0];
    const float* qkv_w    = (const float*)d_in[1];
    const float* qkv_g    = (const float*)d_in[2];
    const float* qkv_b    = (const float*)d_in[3];
    const float* qkv_m    = (const float*)d_in[4];
    const float* qkv_v    = (const float*)d_in[5];
    const float* biases   = (const float*)d_in[6];
    const float* proj_w   = (const float*)d_in[7];
    const float* proj_g   = (const float*)d_in[8];
    const float* proj_b   = (const float*)d_in[9];
    const float* proj_m   = (const float*)d_in[10];
    const float* proj_v   = (const float*)d_in[11];
    float* out = (float*)d_out;

    float* qkv_buf;
    float* att_buf;
    cudaGetSymbolAddress((void**)&qkv_buf, g_qkv);
    cudaGetSymbolAddress((void**)&att_buf, g_att);

    const int smem_bytes = (NN * 197 + NN * KDIM + NN) * (int)sizeof(float);
    cudaFuncSetAttribute(attn_kernel,
                         cudaFuncAttributeMaxDynamicSharedMemorySize, smem_bytes);

    // 1) QKV = x @ qkv_w^T, BN fused.  M=25088, N=2304, K=384
    gemm_tf32_bn<DIMX, QKVD><<<dim3(QKVD / 128, MTOT / 128), 256>>>(
        x, qkv_w, qkv_g, qkv_b, qkv_m, qkv_v, qkv_buf);

    // 2) Attention + softmax + PV + SiLU.  One CTA per (b,h).
    attn_kernel<<<BATCH * NH, 256, smem_bytes>>>(biases);

    // 3) out = silu_att @ proj_w^T, BN fused.  M=25088, N=384, K=1536
    gemm_tf32_bn<VAD, DIMX><<<dim3(DIMX / 128, MTOT / 128), 256>>>(
        att_buf, proj_w, proj_g, proj_b, proj_m, proj_v, out);
}

// round 16
// speedup vs baseline: 1.0011x; 1.0011x over previous
#include <cuda_runtime.h>
#include <math.h>

#define RES   14
#define NN    196          // RES*RES tokens
#define BATCH 128
#define DIMX  384
#define NH    12
#define KDIM  32
#define VDIM  128
#define HDIM  192          // per-head q+k+v = 32+32+128
#define QKVD  2304
#define VAD   1536
#define MTOT  (BATCH*NN)   // 25088

// Scratch (device globals — no allocation allowed in kernel_launch)
__device__ float g_qkv[(size_t)MTOT * QKVD];   // ~231 MB
__device__ float g_att[(size_t)MTOT * VAD];    // ~154 MB

// ---------------------------------------------------------------------------
// tf32 round-to-nearest conversion (unbiased; HW truncation would bias)
// ---------------------------------------------------------------------------
__device__ __forceinline__ unsigned f2tf32(float x) {
    unsigned r;
    asm("cvt.rna.tf32.f32 %0, %1;" : "=r"(r) : "f"(x));
    return r;
}

__device__ __forceinline__ void mma_tf32(float c[4], const unsigned a[4],
                                         const unsigned b[2]) {
    asm volatile(
        "mma.sync.aligned.m16n8k8.row.col.f32.tf32.tf32.f32 "
        "{%0,%1,%2,%3}, {%4,%5,%6,%7}, {%8,%9}, {%0,%1,%2,%3};"
        : "+f"(c[0]), "+f"(c[1]), "+f"(c[2]), "+f"(c[3])
        : "r"(a[0]), "r"(a[1]), "r"(a[2]), "r"(a[3]), "r"(b[0]), "r"(b[1]));
}

// ---------------------------------------------------------------------------
// tf32 tensor-core GEMM + fused BN:
//   C[m][n] = (sum_k A[m][k]*B[n][k]) * inv[n] + add[n]
// A: [M x K] row-major, B (weights): [N x K] row-major == col-major KxN,
// which is exactly mma.sync's .col B operand.
// CTA tile 128x128x32, 8 warps (4m x 2n), warp tile 32x64 (2x8 m16n8k8).
// SMEM staged in fragment order [tile][kstep][lane][reg] with a +2*ks lane
// rotation -> conflict-free scatter STS and conflict-free LDS.128/LDS.64.
// ---------------------------------------------------------------------------
template<int Kdim, int Ndim>
__global__ __launch_bounds__(256, 2)
void gemm_tf32_bn(const float* __restrict__ A,
                  const float* __restrict__ Bm,
                  const float* __restrict__ gamma,
                  const float* __restrict__ beta,
                  const float* __restrict__ mean,
                  const float* __restrict__ var,
                  float* __restrict__ C)
{
    __shared__ unsigned sA[8 * 4 * 32 * 4];   // 16 KB: [mt][ks][lane][reg4]
    __shared__ unsigned sB[16 * 4 * 32 * 2];  // 16 KB: [nt][ks][lane][reg2]
    __shared__ float sInv[128], sAdd[128];

    const int t  = threadIdx.x;
    const int l  = t & 31;
    const int w  = t >> 5;
    const int wm = w & 3;          // 0..3  (m)
    const int wn = w >> 2;         // 0..1  (n)
    const int m0 = blockIdx.y * 128;
    const int n0 = blockIdx.x * 128;

    if (t < 128) {
        float iv = gamma[n0 + t] * rsqrtf(var[n0 + t] + 1e-5f);
        sInv[t] = iv;
        sAdd[t] = beta[n0 + t] - mean[n0 + t] * iv;
    }

    float acc[2][8][4];
    #pragma unroll
    for (int i = 0; i < 2; i++)
        #pragma unroll
        for (int j = 0; j < 8; j++)
            #pragma unroll
            for (int r = 0; r < 4; r++) acc[i][j][r] = 0.f;

    #pragma unroll 1
    for (int k0 = 0; k0 < Kdim; k0 += 32) {
        __syncthreads();   // previous iter's fragment reads done

        // ---- stage A (128x32) into fragment-order smem ----
        #pragma unroll
        for (int p = 0; p < 4; p++) {
            int idx = p * 256 + t;            // 0..1023 float4s
            int row = idx >> 3, c4 = idx & 7;
            float4 v = *reinterpret_cast<const float4*>(
                &A[(size_t)(m0 + row) * Kdim + k0 + c4 * 4]);
            int mt = row >> 4, r = row & 15, ks = c4 >> 1;
            int reg = (r >> 3) + 2 * (c4 & 1);
            unsigned* dst = &sA[(mt * 4 + ks) * 128];
            int pb = (r & 7) * 4 + 2 * ks;    // rotated lane position
            dst[((pb + 0) & 31) * 4 + reg] = f2tf32(v.x);
            dst[((pb + 1) & 31) * 4 + reg] = f2tf32(v.y);
            dst[((pb + 2) & 31) * 4 + reg] = f2tf32(v.z);
            dst[((pb + 3) & 31) * 4 + reg] = f2tf32(v.w);
        }
        // ---- stage B (128x32) ----
        #pragma unroll
        for (int p = 0; p < 4; p++) {
            int idx = p * 256 + t;
            int row = idx >> 3, c4 = idx & 7;
            float4 v = *reinterpret_cast<const float4*>(
                &Bm[(size_t)(n0 + row) * Kdim + k0 + c4 * 4]);
            int nt = row >> 3, nl = row & 7, ks = c4 >> 1;
            int reg = c4 & 1;
            unsigned* dst = &sB[(nt * 4 + ks) * 64];
            int pb = nl * 4 + 2 * ks;
            dst[((pb + 0) & 31) * 2 + reg] = f2tf32(v.x);
            dst[((pb + 1) & 31) * 2 + reg] = f2tf32(v.y);
            dst[((pb + 2) & 31) * 2 + reg] = f2tf32(v.z);
            dst[((pb + 3) & 31) * 2 + reg] = f2tf32(v.w);
        }
        __syncthreads();

        // ---- 4 k-steps of m16n8k8 ----
        #pragma unroll
        for (int ks = 0; ks < 4; ks++) {
            const int rl = (l + 2 * ks) & 31;
            unsigned a[2][4], b[8][2];
            #pragma unroll
            for (int i = 0; i < 2; i++) {
                uint4 av = *reinterpret_cast<const uint4*>(
                    &sA[(((wm * 2 + i) * 4 + ks) * 32 + rl) * 4]);
                a[i][0] = av.x; a[i][1] = av.y; a[i][2] = av.z; a[i][3] = av.w;
            }
            #pragma unroll
            for (int j = 0; j < 8; j++) {
                uint2 bv = *reinterpret_cast<const uint2*>(
                    &sB[(((wn * 8 + j) * 4 + ks) * 32 + rl) * 2]);
                b[j][0] = bv.x; b[j][1] = bv.y;
            }
            #pragma unroll
            for (int i = 0; i < 2; i++)
                #pragma unroll
                for (int j = 0; j < 8; j++)
                    mma_tf32(acc[i][j], a[i], b[j]);
        }
    }

    // ---- BN epilogue ----
    const int gid = l >> 2, tid4 = l & 3;
    #pragma unroll
    for (int i = 0; i < 2; i++) {
        const int m = m0 + wm * 32 + i * 16 + gid;
        #pragma unroll
        for (int j = 0; j < 8; j++) {
            const int nb = wn * 64 + j * 8 + tid4 * 2;
            const float i0 = sInv[nb], a0 = sAdd[nb];
            const float i1 = sInv[nb + 1], a1 = sAdd[nb + 1];
            float2 o0, o1;
            o0.x = acc[i][j][0] * i0 + a0;
            o0.y = acc[i][j][1] * i1 + a1;
            o1.x = acc[i][j][2] * i0 + a0;
            o1.y = acc[i][j][3] * i1 + a1;
            *reinterpret_cast<float2*>(&C[(size_t)m * Ndim + n0 + nb]) = o0;
            *reinterpret_cast<float2*>(&C[(size_t)(m + 8) * Ndim + n0 + nb]) = o1;
        }
    }
}

// ---------------------------------------------------------------------------
// Attention: one CTA per (batch, head). 256 threads; thread i<196 owns query i.
// smem: scores[196][197] (stride-197 => bank-conflict-free), kv staging, bias.
// Softmax kept unnormalized (1/sum folded into PV). SiLU fused into store.
// ---------------------------------------------------------------------------
__global__ __launch_bounds__(256, 1)
void attn_kernel(const float* __restrict__ biases)
{
    extern __shared__ float sh[];
    float* s_sh    = sh;                      // 196*197 scores (also q staging)
    float* kv_sh   = sh + NN * 197;           // 196*32 (k, reused for v tiles)
    float* bias_sh = kv_sh + NN * KDIM;       // 196

    const int bh = blockIdx.x;
    const int b  = bh / NH;
    const int h  = bh % NH;
    const int t  = threadIdx.x;

    const float* base = g_qkv + (size_t)b * NN * QKVD + h * HDIM;

    for (int i = t; i < NN; i += 256) bias_sh[i] = biases[h * NN + i];
    for (int e = t; e < NN * KDIM; e += 256) {
        int n = e >> 5, d = e & 31;
        s_sh[e]  = base[(size_t)n * QKVD + d];          // q
        kv_sh[e] = base[(size_t)n * QKVD + KDIM + d];   // k
    }
    __syncthreads();

    float q[KDIM];
    if (t < NN) {
        #pragma unroll
        for (int d = 0; d < KDIM; d++) q[d] = s_sh[t * KDIM + d];
    }
    __syncthreads();   // s_sh free for scores now

    float* srow = s_sh + t * 197;
    float rmax = -1e30f;
    if (t < NN) {
        const int yi = t / RES, xi = t % RES;
        int j = 0;
        for (int yj = 0; yj < RES; yj++) {
            const int dy = abs(yi - yj) * RES;
            #pragma unroll
            for (int xj = 0; xj < RES; xj++, j++) {
                float acc = 0.f;
                const float* krow = kv_sh + j * KDIM;   // broadcast read
                #pragma unroll
                for (int d = 0; d < KDIM; d++)
                    acc = fmaf(q[d], krow[d], acc);
                float val = acc * 0.17677669529663687f + bias_sh[dy + abs(xi - xj)];
                srow[j] = val;
                rmax = fmaxf(rmax, val);
            }
        }
    }

    float rs = 0.f;
    if (t < NN) {
        for (int j = 0; j < NN; j++) {
            float e = __expf(srow[j] - rmax);
            srow[j] = e;
            rs += e;
        }
        rs = 1.0f / rs;
    }
    __syncthreads();   // everyone done with kv_sh(k) before v overwrites it

    float* out_base = g_att + (size_t)b * NN * VAD + h * VDIM;
    for (int dt = 0; dt < VDIM; dt += 16) {
        for (int e = t; e < NN * 16; e += 256) {
            int n = e >> 4, d = e & 15;
            kv_sh[e] = base[(size_t)n * QKVD + 2 * KDIM + dt + d];
        }
        __syncthreads();
        if (t < NN) {
            float acc[16];
            #pragma unroll
            for (int d = 0; d < 16; d++) acc[d] = 0.f;
            for (int j = 0; j < NN; j++) {
                float wgt = srow[j];                   // stride-197: conflict-free
                const float* vrow = kv_sh + j * 16;    // broadcast read
                #pragma unroll
                for (int d = 0; d < 16; d++)
                    acc[d] = fmaf(wgt, vrow[d], acc[d]);
            }
            #pragma unroll
            for (int d = 0; d < 16; d++) {
                float x = acc[d] * rs;
                float sig = 1.0f / (1.0f + __expf(-x));
                out_base[(size_t)t * VAD + dt + d] = x * sig;   // SiLU fused
            }
        }
        __syncthreads();
    }
}

// ---------------------------------------------------------------------------
extern "C" void kernel_launch(void* const* d_in, const int* in_sizes, int n_in,
                              void* d_out, int out_size)
{
    const float* x        = (const float*)d_in[0];
    const float* qkv_w    = (const float*)d_in[1];
    const float* qkv_g    = (const float*)d_in[2];
    const float* qkv_b    = (const float*)d_in[3];
    const float* qkv_m    = (const float*)d_in[4];
    const float* qkv_v    = (const float*)d_in[5];
    const float* biases   = (const float*)d_in[6];
    const float* proj_w   = (const float*)d_in[7];
    const float* proj_g   = (const float*)d_in[8];
    const float* proj_b   = (const float*)d_in[9];
    const float* proj_m   = (const float*)d_in[10];
    const float* proj_v   = (const float*)d_in[11];
    float* out = (float*)d_out;

    float* qkv_buf;
    float* att_buf;
    cudaGetSymbolAddress((void**)&qkv_buf, g_qkv);
    cudaGetSymbolAddress((void**)&att_buf, g_att);

    const int smem_bytes = (NN * 197 + NN * KDIM + NN) * (int)sizeof(float);
    cudaFuncSetAttribute(attn_kernel,
                         cudaFuncAttributeMaxDynamicSharedMemorySize, smem_bytes);

    // 1) QKV = x @ qkv_w^T, BN fused.  M=25088, N=2304, K=384
    gemm_tf32_bn<DIMX, QKVD><<<dim3(QKVD / 128, MTOT / 128), 256>>>(
        x, qkv_w, qkv_g, qkv_b, qkv_m, qkv_v, qkv_buf);

    // 2) Attention + softmax + PV + SiLU.  One CTA per (b,h).
    attn_kernel<<<BATCH * NH, 256, smem_bytes>>>(biases);

    // 3) out = silu_att @ proj_w^T, BN fused.  M=25088, N=384, K=1536
    gemm_tf32_bn<VAD, DIMX><<<dim3(DIMX / 128, MTOT / 128), 256>>>(
        att_buf, proj_w, proj_g, proj_b, proj_m, proj_v, out);
}

// round 17
// speedup vs baseline: 1.6108x; 1.6091x over previous
#include <cuda_runtime.h>
#include <math.h>

#define RES   14
#define NN    196          // RES*RES tokens
#define BATCH 128
#define DIMX  384
#define NH    12
#define KDIM  32
#define VDIM  128
#define HDIM  192          // per-head q+k+v = 32+32+128
#define QKVD  2304
#define VAD   1536
#define MTOT  (BATCH*NN)   // 25088

// Scratch (device globals — no allocation allowed in kernel_launch)
__device__ float g_qkv[(size_t)MTOT * QKVD];   // ~231 MB
__device__ float g_att[(size_t)MTOT * VAD];    // ~154 MB

// ---------------------------------------------------------------------------
__device__ __forceinline__ unsigned f2tf32(float x) {
    unsigned r;
    asm("cvt.rna.tf32.f32 %0, %1;" : "=r"(r) : "f"(x));
    return r;
}

__device__ __forceinline__ void mma_tf32(float c[4], const unsigned a[4],
                                         const unsigned b[2]) {
    asm volatile(
        "mma.sync.aligned.m16n8k8.row.col.f32.tf32.tf32.f32 "
        "{%0,%1,%2,%3}, {%4,%5,%6,%7}, {%8,%9}, {%0,%1,%2,%3};"
        : "+f"(c[0]), "+f"(c[1]), "+f"(c[2]), "+f"(c[3])
        : "r"(a[0]), "r"(a[1]), "r"(a[2]), "r"(a[3]), "r"(b[0]), "r"(b[1]));
}

// ---------------------------------------------------------------------------
// tf32 tensor-core GEMM + fused BN (unchanged from round 16)
// ---------------------------------------------------------------------------
template<int Kdim, int Ndim>
__global__ __launch_bounds__(256, 2)
void gemm_tf32_bn(const float* __restrict__ A,
                  const float* __restrict__ Bm,
                  const float* __restrict__ gamma,
                  const float* __restrict__ beta,
                  const float* __restrict__ mean,
                  const float* __restrict__ var,
                  float* __restrict__ C)
{
    __shared__ unsigned sA[8 * 4 * 32 * 4];   // [mt][ks][lane][reg4]
    __shared__ unsigned sB[16 * 4 * 32 * 2];  // [nt][ks][lane][reg2]
    __shared__ float sInv[128], sAdd[128];

    const int t  = threadIdx.x;
    const int l  = t & 31;
    const int w  = t >> 5;
    const int wm = w & 3;
    const int wn = w >> 2;
    const int m0 = blockIdx.y * 128;
    const int n0 = blockIdx.x * 128;

    if (t < 128) {
        float iv = gamma[n0 + t] * rsqrtf(var[n0 + t] + 1e-5f);
        sInv[t] = iv;
        sAdd[t] = beta[n0 + t] - mean[n0 + t] * iv;
    }

    float acc[2][8][4];
    #pragma unroll
    for (int i = 0; i < 2; i++)
        #pragma unroll
        for (int j = 0; j < 8; j++)
            #pragma unroll
            for (int r = 0; r < 4; r++) acc[i][j][r] = 0.f;

    #pragma unroll 1
    for (int k0 = 0; k0 < Kdim; k0 += 32) {
        __syncthreads();
        #pragma unroll
        for (int p = 0; p < 4; p++) {
            int idx = p * 256 + t;
            int row = idx >> 3, c4 = idx & 7;
            float4 v = *reinterpret_cast<const float4*>(
                &A[(size_t)(m0 + row) * Kdim + k0 + c4 * 4]);
            int mt = row >> 4, r = row & 15, ks = c4 >> 1;
            int reg = (r >> 3) + 2 * (c4 & 1);
            unsigned* dst = &sA[(mt * 4 + ks) * 128];
            int pb = (r & 7) * 4 + 2 * ks;
            dst[((pb + 0) & 31) * 4 + reg] = f2tf32(v.x);
            dst[((pb + 1) & 31) * 4 + reg] = f2tf32(v.y);
            dst[((pb + 2) & 31) * 4 + reg] = f2tf32(v.z);
            dst[((pb + 3) & 31) * 4 + reg] = f2tf32(v.w);
        }
        #pragma unroll
        for (int p = 0; p < 4; p++) {
            int idx = p * 256 + t;
            int row = idx >> 3, c4 = idx & 7;
            float4 v = *reinterpret_cast<const float4*>(
                &Bm[(size_t)(n0 + row) * Kdim + k0 + c4 * 4]);
            int nt = row >> 3, nl = row & 7, ks = c4 >> 1;
            int reg = c4 & 1;
            unsigned* dst = &sB[(nt * 4 + ks) * 64];
            int pb = nl * 4 + 2 * ks;
            dst[((pb + 0) & 31) * 2 + reg] = f2tf32(v.x);
            dst[((pb + 1) & 31) * 2 + reg] = f2tf32(v.y);
            dst[((pb + 2) & 31) * 2 + reg] = f2tf32(v.z);
            dst[((pb + 3) & 31) * 2 + reg] = f2tf32(v.w);
        }
        __syncthreads();

        #pragma unroll
        for (int ks = 0; ks < 4; ks++) {
            const int rl = (l + 2 * ks) & 31;
            unsigned a[2][4], b[8][2];
            #pragma unroll
            for (int i = 0; i < 2; i++) {
                uint4 av = *reinterpret_cast<const uint4*>(
                    &sA[(((wm * 2 + i) * 4 + ks) * 32 + rl) * 4]);
                a[i][0] = av.x; a[i][1] = av.y; a[i][2] = av.z; a[i][3] = av.w;
            }
            #pragma unroll
            for (int j = 0; j < 8; j++) {
                uint2 bv = *reinterpret_cast<const uint2*>(
                    &sB[(((wn * 8 + j) * 4 + ks) * 32 + rl) * 2]);
                b[j][0] = bv.x; b[j][1] = bv.y;
            }
            #pragma unroll
            for (int i = 0; i < 2; i++)
                #pragma unroll
                for (int j = 0; j < 8; j++)
                    mma_tf32(acc[i][j], a[i], b[j]);
        }
    }

    const int gid = l >> 2, tid4 = l & 3;
    #pragma unroll
    for (int i = 0; i < 2; i++) {
        const int m = m0 + wm * 32 + i * 16 + gid;
        #pragma unroll
        for (int j = 0; j < 8; j++) {
            const int nb = wn * 64 + j * 8 + tid4 * 2;
            const float i0 = sInv[nb], a0 = sAdd[nb];
            const float i1 = sInv[nb + 1], a1 = sAdd[nb + 1];
            float2 o0, o1;
            o0.x = acc[i][j][0] * i0 + a0;
            o0.y = acc[i][j][1] * i1 + a1;
            o1.x = acc[i][j][2] * i0 + a0;
            o1.y = acc[i][j][3] * i1 + a1;
            *reinterpret_cast<float2*>(&C[(size_t)m * Ndim + n0 + nb]) = o0;
            *reinterpret_cast<float2*>(&C[(size_t)(m + 8) * Ndim + n0 + nb]) = o1;
        }
    }
}

// ---------------------------------------------------------------------------
// Tensor-core attention. One CTA per (b,h), 8 warps.
// Queries padded 196->208 (13 m16 tiles), keys padded 196->200 (25 n8 tiles).
// ---------------------------------------------------------------------------
#define SST   201                    // score row stride (floats)
#define SWORDS (208 * SST)           // 41808
#define QF_WORDS (13 * 4 * 128)      // 6656
#define KF_WORDS (25 * 4 * 64)       // 6400
#define FRAG_WORDS 13312             // max(QF+KF, V frags 16*13*64)
#define ATT_SMEM_WORDS (SWORDS + FRAG_WORDS + 196 + 208)

__global__ __launch_bounds__(256, 1)
void attn_tc_kernel(const float* __restrict__ biases)
{
    extern __shared__ float sh[];
    float*    S  = sh;                                   // [208][201]
    unsigned* Qf = reinterpret_cast<unsigned*>(sh + SWORDS);
    unsigned* Kf = Qf + QF_WORDS;
    unsigned* Vf = Qf;                                   // phase-disjoint reuse
    float*    bias_sh = reinterpret_cast<float*>(Qf + FRAG_WORDS);
    int*      yx = reinterpret_cast<int*>(bias_sh + 196);

    const int bh = blockIdx.x;
    const int b  = bh / NH;
    const int h  = bh % NH;
    const int t  = threadIdx.x;
    const int l  = t & 31;
    const int w  = t >> 5;
    const int gid = l >> 2, tid4 = l & 3;

    const float* base = g_qkv + (size_t)b * NN * QKVD + h * HDIM;

    // ---- tables ----
    for (int i = t; i < 196; i += 256) bias_sh[i] = biases[h * NN + i];
    for (int i = t; i < 208; i += 256) yx[i] = (i / 14) * 16 + (i % 14);

    // ---- stage Q as A-fragments (rows >=196 zero) ----
    for (int idx = t; idx < 208 * 8; idx += 256) {
        int row = idx >> 3, c4 = idx & 7;
        float4 v = make_float4(0.f, 0.f, 0.f, 0.f);
        if (row < 196)
            v = *reinterpret_cast<const float4*>(&base[(size_t)row * QKVD + c4 * 4]);
        int mt = row >> 4, r = row & 15, ks = c4 >> 1;
        int reg = (r >> 3) + 2 * (c4 & 1);
        unsigned* dst = &Qf[(mt * 4 + ks) * 128];
        int pb = (r & 7) * 4 + 2 * ks;
        dst[((pb + 0) & 31) * 4 + reg] = f2tf32(v.x);
        dst[((pb + 1) & 31) * 4 + reg] = f2tf32(v.y);
        dst[((pb + 2) & 31) * 4 + reg] = f2tf32(v.z);
        dst[((pb + 3) & 31) * 4 + reg] = f2tf32(v.w);
    }
    // ---- stage K as B-fragments (tokens >=196 zero) ----
    for (int idx = t; idx < 200 * 8; idx += 256) {
        int row = idx >> 3, c4 = idx & 7;
        float4 v = make_float4(0.f, 0.f, 0.f, 0.f);
        if (row < 196)
            v = *reinterpret_cast<const float4*>(
                &base[(size_t)row * QKVD + KDIM + c4 * 4]);
        int nt = row >> 3, nl = row & 7, ks = c4 >> 1;
        int reg = c4 & 1;
        unsigned* dst = &Kf[(nt * 4 + ks) * 64];
        int pb = nl * 4 + 2 * ks;
        dst[((pb + 0) & 31) * 2 + reg] = f2tf32(v.x);
        dst[((pb + 1) & 31) * 2 + reg] = f2tf32(v.y);
        dst[((pb + 2) & 31) * 2 + reg] = f2tf32(v.z);
        dst[((pb + 3) & 31) * 2 + reg] = f2tf32(v.w);
    }
    __syncthreads();

    // ---- QK^T: 13 x 25 tiles, linear warp assignment ----
    const float scale = 0.17677669529663687f;
    for (int T = w; T < 13 * 25; T += 8) {
        int mt = T / 25, nt = T % 25;
        float c[4] = {0.f, 0.f, 0.f, 0.f};
        #pragma unroll
        for (int ks = 0; ks < 4; ks++) {
            int rl = (l + 2 * ks) & 31;
            uint4 av = *reinterpret_cast<const uint4*>(
                &Qf[((mt * 4 + ks) * 32 + rl) * 4]);
            uint2 bv = *reinterpret_cast<const uint2*>(
                &Kf[((nt * 4 + ks) * 32 + rl) * 2]);
            unsigned a[4] = {av.x, av.y, av.z, av.w};
            unsigned bb[2] = {bv.x, bv.y};
            mma_tf32(c, a, bb);
        }
        int i0 = mt * 16 + gid, i1 = i0 + 8;
        int j0 = nt * 8 + 2 * tid4, j1 = j0 + 1;
        float s0 = c[0] * scale, s1 = c[1] * scale;
        float s2 = c[2] * scale, s3 = c[3] * scale;
        bool jv0 = j0 < 196, jv1 = j1 < 196;
        int vj0 = yx[j0], vj1 = yx[j1];
        if (i0 < 196) {
            int vi = yx[i0];
            if (jv0) s0 += bias_sh[abs((vi >> 4) - (vj0 >> 4)) * 14 +
                                   abs((vi & 15) - (vj0 & 15))];
            if (jv1) s1 += bias_sh[abs((vi >> 4) - (vj1 >> 4)) * 14 +
                                   abs((vi & 15) - (vj1 & 15))];
        }
        if (i1 < 196) {
            int vi = yx[i1];
            if (jv0) s2 += bias_sh[abs((vi >> 4) - (vj0 >> 4)) * 14 +
                                   abs((vi & 15) - (vj0 & 15))];
            if (jv1) s3 += bias_sh[abs((vi >> 4) - (vj1 >> 4)) * 14 +
                                   abs((vi & 15) - (vj1 & 15))];
        }
        if (!jv0) { s0 = -1e30f; s2 = -1e30f; }
        if (!jv1) { s1 = -1e30f; s3 = -1e30f; }
        S[i0 * SST + j0] = s0; S[i0 * SST + j1] = s1;
        S[i1 * SST + j0] = s2; S[i1 * SST + j1] = s3;
    }
    __syncthreads();

    // ---- row softmax; fold 1/sum and tf32 cvt into P (in place) ----
    if (t < 196) {
        float* row = S + t * SST;
        float mx = -1e30f;
        for (int j = 0; j < 196; j++) mx = fmaxf(mx, row[j]);
        float s = 0.f;
        for (int j = 0; j < 196; j++) {
            float e = __expf(row[j] - mx);
            s += e;
            row[j] = e;
        }
        float rs = 1.0f / s;
        for (int j = 0; j < 196; j++)
            row[j] = __uint_as_float(f2tf32(row[j] * rs));
        row[196] = 0.f; row[197] = 0.f; row[198] = 0.f; row[199] = 0.f;
    } else if (t < 208) {
        float* row = S + t * SST;
        for (int j = 0; j < 200; j++) row[j] = 0.f;
    }

    // ---- PV: warp split 4(m-groups) x 2(n-halves) ----
    const int wm2 = w & 3;      // mt = wm2 + 4*i
    const int wn2 = w >> 2;     // d tiles wn2*8 + j
    float acc[4][8][4];
    #pragma unroll
    for (int i = 0; i < 4; i++)
        #pragma unroll
        for (int j = 0; j < 8; j++)
            #pragma unroll
            for (int r = 0; r < 4; r++) acc[i][j][r] = 0.f;

    #pragma unroll 1
    for (int chunk = 0; chunk < 2; chunk++) {
        const int tok0 = chunk ? 104 : 0;
        const int nks  = chunk ? 12 : 13;
        // stage V chunk as B-fragments [nt16][ks<=13][lane][reg2]
        {
            int tl = l & 7, dq = l >> 3;
            for (int g = w; g < nks; g += 8) {
                int gt = tok0 + g * 8 + tl;
                bool valid = gt < 196;
                const float* vp = base + (size_t)gt * QKVD + 2 * KDIM;
                #pragma unroll
                for (int it = 0; it < 8; it++) {
                    int d0 = it * 16 + dq * 4;
                    float4 v = valid
                        ? *reinterpret_cast<const float4*>(&vp[d0])
                        : make_float4(0.f, 0.f, 0.f, 0.f);
                    float vv[4] = {v.x, v.y, v.z, v.w};
                    #pragma unroll
                    for (int i2 = 0; i2 < 4; i2++) {
                        int d = d0 + i2;
                        Vf[(((d >> 3) * 13 + g) * 32 + (d & 7) * 4 + (tl & 3)) * 2 +
                           (tl >> 2)] = f2tf32(vv[i2]);
                    }
                }
            }
        }
        __syncthreads();   // V staged; (chunk0) also publishes softmax P

        for (int ks = 0; ks < nks; ks++) {
            unsigned bb[8][2];
            #pragma unroll
            for (int j = 0; j < 8; j++) {
                uint2 bv = *reinterpret_cast<const uint2*>(
                    &Vf[(((wn2 * 8 + j) * 13 + ks) * 32 + l) * 2]);
                bb[j][0] = bv.x; bb[j][1] = bv.y;
            }
            const int cc = tok0 + ks * 8 + tid4;
            #pragma unroll
            for (int i = 0; i < 4; i++) {
                int mt = wm2 + 4 * i;
                if (mt < 13) {
                    int r0 = mt * 16 + gid;
                    unsigned a[4];
                    a[0] = __float_as_uint(S[r0 * SST + cc]);
                    a[1] = __float_as_uint(S[(r0 + 8) * SST + cc]);
                    a[2] = __float_as_uint(S[r0 * SST + cc + 4]);
                    a[3] = __float_as_uint(S[(r0 + 8) * SST + cc + 4]);
                    #pragma unroll
                    for (int j = 0; j < 8; j++)
                        mma_tf32(acc[i][j], a, bb[j]);
                }
            }
        }
        __syncthreads();   // chunk0 reads done before chunk1 overwrites Vf
    }

    // ---- SiLU + store (rows < 196 only) ----
    float* outp = g_att + (size_t)b * NN * VAD + h * VDIM;
    #pragma unroll
    for (int i = 0; i < 4; i++) {
        int mt = wm2 + 4 * i;
        if (mt < 13) {
            int r0 = mt * 16 + gid;
            #pragma unroll
            for (int j = 0; j < 8; j++) {
                int d = (wn2 * 8 + j) * 8 + 2 * tid4;
                if (r0 < 196) {
                    float2 o;
                    float x0 = acc[i][j][0];
                    float x1 = acc[i][j][1];
                    o.x = x0 * (1.0f / (1.0f + __expf(-x0)));
                    o.y = x1 * (1.0f / (1.0f + __expf(-x1)));
                    *reinterpret_cast<float2*>(&outp[(size_t)r0 * VAD + d]) = o;
                }
                int r1 = r0 + 8;
                if (r1 < 196) {
                    float2 o;
                    float x0 = acc[i][j][2];
                    float x1 = acc[i][j][3];
                    o.x = x0 * (1.0f / (1.0f + __expf(-x0)));
                    o.y = x1 * (1.0f / (1.0f + __expf(-x1)));
                    *reinterpret_cast<float2*>(&outp[(size_t)r1 * VAD + d]) = o;
                }
            }
        }
    }
}

// ---------------------------------------------------------------------------
extern "C" void kernel_launch(void* const* d_in, const int* in_sizes, int n_in,
                              void* d_out, int out_size)
{
    const float* x        = (const float*)d_in[0];
    const float* qkv_w    = (const float*)d_in[1];
    const float* qkv_g    = (const float*)d_in[2];
    const float* qkv_b    = (const float*)d_in[3];
    const float* qkv_m    = (const float*)d_in[4];
    const float* qkv_v    = (const float*)d_in[5];
    const float* biases   = (const float*)d_in[6];
    const float* proj_w   = (const float*)d_in[7];
    const float* proj_g   = (const float*)d_in[8];
    const float* proj_b   = (const float*)d_in[9];
    const float* proj_m   = (const float*)d_in[10];
    const float* proj_v   = (const float*)d_in[11];
    float* out = (float*)d_out;

    float* qkv_buf;
    float* att_buf;
    cudaGetSymbolAddress((void**)&qkv_buf, g_qkv);
    cudaGetSymbolAddress((void**)&att_buf, g_att);

    const int att_smem = ATT_SMEM_WORDS * (int)sizeof(float);  // ~222 KB
    cudaFuncSetAttribute(attn_tc_kernel,
                         cudaFuncAttributeMaxDynamicSharedMemorySize, att_smem);

    // 1) QKV = x @ qkv_w^T, BN fused.  M=25088, N=2304, K=384
    gemm_tf32_bn<DIMX, QKVD><<<dim3(QKVD / 128, MTOT / 128), 256>>>(
        x, qkv_w, qkv_g, qkv_b, qkv_m, qkv_v, qkv_buf);

    // 2) Tensor-core attention + softmax + PV + SiLU.  One CTA per (b,h).
    attn_tc_kernel<<<BATCH * NH, 256, att_smem>>>(biases);

    // 3) out = silu_att @ proj_w^T, BN fused.  M=25088, N=384, K=1536
    gemm_tf32_bn<VAD, DIMX><<<dim3(DIMX / 128, MTOT / 128), 256>>>(
        att_buf, proj_w, proj_g, proj_b, proj_m, proj_v, out);
}